// round 12
// baseline (speedup 1.0000x reference)
#include <cuda_runtime.h>
#include <cuda_fp16.h>
#include <math.h>
#include <stdint.h>

#define W_ 192
#define H_ 192
#define D_ 160
#define HW_ (H_ * W_)
#define CHUNK 80
#define NPAIRS  42
#define NBLOCKS (6 * 24 * 4)

#define NTHREADS 256
#define NPROD    128

#define BAR_FULL0  1
#define BAR_FULL1  2
#define BAR_EMPTY0 3
#define BAR_EMPTY1 4
#define BAR_PROD   5
#define BAR_CONS   6

// tile geometry: 32 x 8 outputs, halo 36 x 12
#define HROWS 12
#define TROWF 480              /* floats per img plane: 12*40 */
#define TPLANEF 960            /* floats per plane (2 imgs) */
#define TPAIRF 1920            /* floats per pair buffer */
#define NPAIRS_LD 432          /* 12*18*2 8B pairs per plane */

// rs layout (plane-interleaved): [ch(5)][row(12)][x2(16)][plane(2)] of __half2
#define RSCH 384               /* ch stride in half2: 12*16*2 */
#define RSROW 32               /* row stride in half2 */
#define RSQ 1920               /* per-q stride in half2 */

// ys layout: [ch(5)][outrow(8)][x2(16)][plane(2)] of __half2
#define YSCH 256               /* ch stride in half2: 8*16*2 */
#define YSROW 32               /* row stride in half2 */
#define YSQ 1280               /* per-q stride in half2 */

__device__ double   g_acc;
__device__ unsigned g_cnt;

static __device__ __forceinline__ void bar_sync_n(int id, int cnt) {
    asm volatile("bar.sync %0, %1;" :: "r"(id), "r"(cnt) : "memory");
}
static __device__ __forceinline__ void bar_arrive_n(int id, int cnt) {
    asm volatile("bar.arrive %0, %1;" :: "r"(id), "r"(cnt) : "memory");
}
static __device__ __forceinline__ void cp_async8(uint32_t dst, const float* src,
                                                 unsigned srcsz) {
    asm volatile("cp.async.ca.shared.global [%0], [%1], 8, %2;"
                 :: "r"(dst), "l"(src), "r"(srcsz) : "memory");
}
static __device__ __forceinline__ void cp_commit() {
    asm volatile("cp.async.commit_group;" ::: "memory");
}
static __device__ __forceinline__ void cp_wait2() {
    asm volatile("cp.async.wait_group 2;" ::: "memory");
}
// 8B shared load of two adjacent half2 (plane0, plane1)
static __device__ __forceinline__ void lds_h2x2(const __half2* p,
                                                __half2& a, __half2& b) {
    uint2 u = *reinterpret_cast<const uint2*>(p);
    a = *reinterpret_cast<__half2*>(&u.x);
    b = *reinterpret_cast<__half2*>(&u.y);
}
static __device__ __forceinline__ void sts_h2x2(__half2* p,
                                                __half2 a, __half2 b) {
    union { __half2 h[2]; uint2 u; } pk;
    pk.h[0] = a; pk.h[1] = b;
    *reinterpret_cast<uint2*>(p) = pk.u;
}

__global__ void __launch_bounds__(NTHREADS, 2)
lncc_k(const float* __restrict__ src, const float* __restrict__ tgt,
       float* __restrict__ out)
{
    // tile: 3 pair-buffers x 2 planes x [img][haloRow(12)][col(36 pad 40)] fp32
    __shared__ float tile[3][2][2][HROWS][40];
    // rs: 2 buffers, plane-interleaved fp16 x-sums
    __shared__ __align__(16) __half2 rs[2][RSQ];
    // ys: 2 buffers, plane-interleaved fp16 xy-sums
    __shared__ __align__(16) __half2 ys[2][YSQ];
    __shared__ float wsum[8];

    const int tid = threadIdx.x;
    const int x0  = blockIdx.x * 32;
    const int y0  = blockIdx.y * 8;
    const int b   = blockIdx.z >> 1;
    const int z0  = (blockIdx.z & 1) * CHUNK;
    const int zstart = z0 - 2;

    const float* baseS = src + (size_t)b * (D_ * HW_);
    const float* baseT = tgt + (size_t)b * (D_ * HW_);

    float acc = 0.f;

    if (tid < NPROD) {
        // ========================= PRODUCER (128) =========================
        uint32_t soffb[4];
        const float* gbase[4];
        unsigned vmask = 0, umask = 0;
        #pragma unroll
        for (int sl = 0; sl < 4; sl++) {
            soffb[sl] = 0; gbase[sl] = baseS;
            const int i = tid + NPROD * sl;
            if (i < NPAIRS_LD) {
                umask |= 1u << sl;
                const int img = (i >= 216) ? 1 : 0;
                const int j   = i - img * 216;
                const int row = j / 18;
                const int pc  = j - row * 18;
                soffb[sl] = (uint32_t)(img * TROWF + row * 40 + pc * 2) * 4u;
                const int gy = y0 + row - 2;
                const int gx = x0 + pc * 2 - 2;
                const bool v = ((unsigned)gy < (unsigned)H_) &&
                               ((unsigned)gx < (unsigned)W_);
                if (v) vmask |= 1u << sl;
                gbase[sl] = (img ? baseT : baseS) + (v ? (gy * W_ + gx) : 0);
            }
        }

        const uint32_t sbase =
            (uint32_t)__cvta_generic_to_shared(&tile[0][0][0][0][0]);

        auto issue_pair = [&](int m) {
            const uint32_t pb = sbase + (uint32_t)(m % 3) * (TPAIRF * 4u);
            #pragma unroll
            for (int pl = 0; pl < 2; pl++) {
                const int zp   = zstart + 2 * m + pl;
                const bool zin = (unsigned)zp < (unsigned)D_;
                const int zoff = zin ? zp * HW_ : 0;
                const uint32_t tb = pb + (uint32_t)pl * (TPLANEF * 4u);
                #pragma unroll
                for (int sl = 0; sl < 4; sl++) {
                    if (umask & (1u << sl)) {
                        unsigned sz = (zin && (vmask & (1u << sl))) ? 8u : 0u;
                        cp_async8(tb + soffb[sl], gbase[sl] + zoff, sz);
                    }
                }
            }
            cp_commit();
        };

        // x-phase item covering BOTH planes of (row r, group g)
        auto xpair = [&](const float* pbuf, __half2* rsq, int item) {
            const int r = item >> 3;
            const int g = item & 7;
            const float* base0 = pbuf + r * 40 + 4 * g;
            __half2 keep[5][2];
            #pragma unroll
            for (int pl = 0; pl < 2; pl++) {
                const float* rowS = base0 + pl * TPLANEF;
                const float* rowT = rowS + TROWF;
                float4 a0 = *(const float4*)(rowS);
                float4 a1 = *(const float4*)(rowS + 4);
                float4 b0 = *(const float4*)(rowT);
                float4 b1 = *(const float4*)(rowT + 4);
                float sc[8] = {a0.x,a0.y,a0.z,a0.w,a1.x,a1.y,a1.z,a1.w};
                float tc[8] = {b0.x,b0.y,b0.z,b0.w,b1.x,b1.y,b1.z,b1.w};

                float V[5][4];
                {
                    float S0=0.f, T0=0.f, SS0=0.f, TT0=0.f, ST0=0.f;
                    #pragma unroll
                    for (int j = 0; j < 5; j++) {
                        S0 += sc[j]; T0 += tc[j];
                        SS0 = fmaf(sc[j], sc[j], SS0);
                        TT0 = fmaf(tc[j], tc[j], TT0);
                        ST0 = fmaf(sc[j], tc[j], ST0);
                    }
                    V[0][0]=S0; V[1][0]=T0; V[2][0]=SS0; V[3][0]=TT0; V[4][0]=ST0;
                    #pragma unroll
                    for (int w = 1; w < 4; w++) {
                        V[0][w] = V[0][w-1] - sc[w-1] + sc[w+4];
                        V[1][w] = V[1][w-1] - tc[w-1] + tc[w+4];
                        V[2][w] = V[2][w-1] - sc[w-1]*sc[w-1] + sc[w+4]*sc[w+4];
                        V[3][w] = V[3][w-1] - tc[w-1]*tc[w-1] + tc[w+4]*tc[w+4];
                        V[4][w] = V[4][w-1] - sc[w-1]*tc[w-1] + sc[w+4]*tc[w+4];
                    }
                }
                if (pl == 0) {
                    #pragma unroll
                    for (int c = 0; c < 5; c++) {
                        keep[c][0] = __floats2half2_rn(V[c][0], V[c][1]);
                        keep[c][1] = __floats2half2_rn(V[c][2], V[c][3]);
                    }
                } else {
                    #pragma unroll
                    for (int c = 0; c < 5; c++) {
                        union { __half2 h[4]; uint4 u; } pk;
                        pk.h[0] = keep[c][0];
                        pk.h[1] = __floats2half2_rn(V[c][0], V[c][1]);
                        pk.h[2] = keep[c][1];
                        pk.h[3] = __floats2half2_rn(V[c][2], V[c][3]);
                        *reinterpret_cast<uint4*>(rsq + c * RSCH + r * RSROW + 4 * g)
                            = pk.u;
                    }
                }
            }
        };

        issue_pair(0);
        issue_pair(1);

        for (int k = 0; k < NPAIRS; k++) {
            const int q = k & 1;
            bar_sync_n(BAR_EMPTY0 + q, NTHREADS);
            issue_pair(k + 2);
            cp_wait2();
            bar_sync_n(BAR_PROD, NPROD);

            if (tid < 96)
                xpair(&tile[k % 3][0][0][0][0], &rs[q][0], tid);

            bar_arrive_n(BAR_FULL0 + q, NTHREADS);
        }
    } else {
        // ========================= CONSUMER (128) =========================
        const int ctid = tid - NPROD;
        const int ctx2 = ctid & 15;              // consume: x-pair
        const int cty  = ctid >> 4;              // consume: output row
        const int yc   = ctid >> 4;              // y-phase: channel (ctid/16)
        const int yx2  = ctid & 15;              // y-phase: x2 column

        float2 ring[5][5];      // [slot][ch], x-pair packed (fp32 delay line)
        float2 run[5];
        #pragma unroll
        for (int s = 0; s < 5; s++)
            #pragma unroll
            for (int c = 0; c < 5; c++) ring[s][c] = make_float2(0.f, 0.f);
        #pragma unroll
        for (int c = 0; c < 5; c++) run[c] = make_float2(0.f, 0.f);

        bar_arrive_n(BAR_EMPTY0, NTHREADS);
        bar_arrive_n(BAR_EMPTY1, NTHREADS);

        auto epilogue = [&]() {
            const float inv = 1.f / 125.f;
            #pragma unroll
            for (int e = 0; e < 2; e++) {
                float rS  = e ? run[0].y : run[0].x;
                float rT  = e ? run[1].y : run[1].x;
                float rSS = e ? run[2].y : run[2].x;
                float rTT = e ? run[3].y : run[3].x;
                float rST = e ? run[4].y : run[4].x;
                float sm = rS * inv;
                float tm = rT * inv;
                float sv = fmaf(-sm, sm, rSS * inv);
                float tv = fmaf(-tm, tm, rTT * inv);
                float cr = fmaf(-sm, tm, rST * inv);
                float den = fmaf(sv, tv, 1e-5f);
                acc += __fdividef(cr * cr, den);
            }
        };

        for (int kb = 0; kb < 45; kb += 5) {
            #pragma unroll
            for (int jj = 0; jj < 5; jj++) {
                const int k = kb + jj;
                if (k >= NPAIRS) break;      // 42 = 8*5 + 2
                const int q  = k & 1;
                const int s0 = (2 * jj) % 5;
                const int s1 = (2 * jj + 1) % 5;
                bar_sync_n(BAR_FULL0 + q, NTHREADS);

                // ---- y-phase: threads 0..79, one (ch, x2) column each ----
                if (ctid < 80) {
                    const __half2* col = &rs[q][0] + yc * RSCH + yx2 * 2;
                    __half2* yo = &ys[q][0] + yc * YSCH + yx2 * 2;
                    __half2 h0[5], h1[5];
                    #pragma unroll
                    for (int i = 0; i < 5; i++)
                        lds_h2x2(col + i * RSROW, h0[i], h1[i]);
                    __half2 n0 = __hadd2(__hadd2(__hadd2(h0[0], h0[1]),
                                                 __hadd2(h0[2], h0[3])), h0[4]);
                    __half2 n1 = __hadd2(__hadd2(__hadd2(h1[0], h1[1]),
                                                 __hadd2(h1[2], h1[3])), h1[4]);
                    sts_h2x2(yo, n0, n1);
                    #pragma unroll
                    for (int i = 5; i < 12; i++) {
                        __half2 t0, t1;
                        lds_h2x2(col + i * RSROW, t0, t1);
                        n0 = __hadd2(__hsub2(n0, h0[i % 5]), t0);
                        n1 = __hadd2(__hsub2(n1, h1[i % 5]), t1);
                        h0[i % 5] = t0;
                        h1[i % 5] = t1;
                        sts_h2x2(yo + (i - 4) * YSROW, n0, n1);
                    }
                }
                bar_sync_n(BAR_CONS, 128);       // ys[q] ready
                bar_arrive_n(BAR_EMPTY0 + q, NTHREADS);  // rs[q] free

                // ---- consume: 5 LDS.64 per pair, both planes ----
                __half2 v0[5], v1[5];
                #pragma unroll
                for (int c = 0; c < 5; c++)
                    lds_h2x2(&ys[q][0] + c * YSCH + cty * YSROW + ctx2 * 2,
                             v0[c], v1[c]);

                const bool live = (k >= 2);
                #pragma unroll
                for (int c = 0; c < 5; c++) {
                    float2 f = __half22float2(v0[c]);
                    float2 o = ring[s0][c];
                    run[c].x += f.x - o.x;
                    run[c].y += f.y - o.y;
                    ring[s0][c] = f;
                }
                if (live) epilogue();            // plane 2k
                #pragma unroll
                for (int c = 0; c < 5; c++) {
                    float2 f = __half22float2(v1[c]);
                    float2 o = ring[s1][c];
                    run[c].x += f.x - o.x;
                    run[c].y += f.y - o.y;
                    ring[s1][c] = f;
                }
                if (live) epilogue();            // plane 2k+1
            }
        }
    }

    // ---- block reduction over all 256 threads (producers contribute 0) ----
    __syncthreads();
    #pragma unroll
    for (int o = 16; o > 0; o >>= 1)
        acc += __shfl_xor_sync(0xffffffffu, acc, o);
    if ((tid & 31) == 0) wsum[tid >> 5] = acc;
    __syncthreads();

    if (tid == 0) {
        float bsum = 0.f;
        #pragma unroll
        for (int i = 0; i < 8; i++) bsum += wsum[i];
        atomicAdd(&g_acc, (double)bsum);
        __threadfence();
        unsigned done = atomicAdd(&g_cnt, 1u);
        if (done == NBLOCKS - 1) {
            double total = atomicAdd(&g_acc, 0.0);  // fenced read
            const double n = 2.0 * 160.0 * 192.0 * 192.0;
            float loss = (float)(1.0 - total / n);
            if (isnan(loss) || isinf(loss)) loss = 1.0f;
            out[0] = loss;
            *((volatile double*)&g_acc)   = 0.0;
            *((volatile unsigned*)&g_cnt) = 0u;
        }
    }
}

extern "C" void kernel_launch(void* const* d_in, const int* in_sizes, int n_in,
                              void* d_out, int out_size)
{
    (void)in_sizes; (void)n_in; (void)out_size;
    const float* src = (const float*)d_in[0];
    const float* tgt = (const float*)d_in[1];

    lncc_k<<<dim3(6, 24, 4), NTHREADS>>>(src, tgt, (float*)d_out);
}

// round 13
// speedup vs baseline: 1.0038x; 1.0038x over previous
#include <cuda_runtime.h>
#include <cuda_fp16.h>
#include <math.h>
#include <stdint.h>

#define W_ 192
#define H_ 192
#define D_ 160
#define HW_ (H_ * W_)
#define CHUNK 80
#define NPAIRS  42
#define NBLOCKS (6 * 24 * 4)

#define NTHREADS 256
#define NPROD    128

#define BAR_FULL0  1
#define BAR_FULL1  2
#define BAR_EMPTY0 3
#define BAR_EMPTY1 4
#define BAR_PROD   5
#define BAR_CONS   6

// tile geometry: 32 x 8 outputs, halo 36 x 12
#define HROWS 12
#define TROWF 480              /* floats per img plane: 12*40 */
#define TPLANEF 960            /* floats per plane (2 imgs) */
#define TPAIRF 1920            /* floats per pair buffer */
#define NPAIRS_LD 432          /* 12*18*2 8B pairs per plane */

// rs layout (plane-interleaved): [ch(5)][row(12)][x2(16)][plane(2)] of __half2
#define RSCH 384
#define RSROW 32
#define RSQ 1920

// ys layout: [ch(5)][outrow(8)][x2(16)][plane(2)] of __half2
#define YSCH 256
#define YSROW 32
#define YSQ 1280

__device__ double   g_acc;
__device__ unsigned g_cnt;

static __device__ __forceinline__ void bar_sync_n(int id, int cnt) {
    asm volatile("bar.sync %0, %1;" :: "r"(id), "r"(cnt) : "memory");
}
static __device__ __forceinline__ void bar_arrive_n(int id, int cnt) {
    asm volatile("bar.arrive %0, %1;" :: "r"(id), "r"(cnt) : "memory");
}
static __device__ __forceinline__ void cp_async8(uint32_t dst, const float* src,
                                                 unsigned srcsz) {
    asm volatile("cp.async.ca.shared.global [%0], [%1], 8, %2;"
                 :: "r"(dst), "l"(src), "r"(srcsz) : "memory");
}
static __device__ __forceinline__ void cp_commit() {
    asm volatile("cp.async.commit_group;" ::: "memory");
}
static __device__ __forceinline__ void cp_wait2() {
    asm volatile("cp.async.wait_group 2;" ::: "memory");
}
// 8B shared load of two adjacent half2 (plane0, plane1)
static __device__ __forceinline__ void lds_h2x2(const __half2* p,
                                                __half2& a, __half2& b) {
    uint2 u = *reinterpret_cast<const uint2*>(p);
    a = *reinterpret_cast<__half2*>(&u.x);
    b = *reinterpret_cast<__half2*>(&u.y);
}
static __device__ __forceinline__ void sts_h2x2(__half2* p,
                                                __half2 a, __half2 b) {
    union { __half2 h[2]; uint2 u; } pk;
    pk.h[0] = a; pk.h[1] = b;
    *reinterpret_cast<uint2*>(p) = pk.u;
}

__global__ void __launch_bounds__(NTHREADS, 2)
lncc_k(const float* __restrict__ src, const float* __restrict__ tgt,
       float* __restrict__ out)
{
    __shared__ float tile[3][2][2][HROWS][40];
    __shared__ __align__(16) __half2 rs[2][RSQ];
    __shared__ __align__(16) __half2 ys[2][YSQ];
    __shared__ float wsum[8];

    const int tid = threadIdx.x;
    const int x0  = blockIdx.x * 32;
    const int y0  = blockIdx.y * 8;
    const int b   = blockIdx.z >> 1;
    const int z0  = (blockIdx.z & 1) * CHUNK;
    const int zstart = z0 - 2;

    const float* baseS = src + (size_t)b * (D_ * HW_);
    const float* baseT = tgt + (size_t)b * (D_ * HW_);

    float acc = 0.f;

    if (tid < NPROD) {
        // ========================= PRODUCER (128) =========================
        uint32_t soffb[4];
        const float* gbase[4];
        unsigned vmask = 0, umask = 0;
        #pragma unroll
        for (int sl = 0; sl < 4; sl++) {
            soffb[sl] = 0; gbase[sl] = baseS;
            const int i = tid + NPROD * sl;
            if (i < NPAIRS_LD) {
                umask |= 1u << sl;
                const int img = (i >= 216) ? 1 : 0;
                const int j   = i - img * 216;
                const int row = j / 18;
                const int pc  = j - row * 18;
                soffb[sl] = (uint32_t)(img * TROWF + row * 40 + pc * 2) * 4u;
                const int gy = y0 + row - 2;
                const int gx = x0 + pc * 2 - 2;
                const bool v = ((unsigned)gy < (unsigned)H_) &&
                               ((unsigned)gx < (unsigned)W_);
                if (v) vmask |= 1u << sl;
                gbase[sl] = (img ? baseT : baseS) + (v ? (gy * W_ + gx) : 0);
            }
        }

        const uint32_t sbase =
            (uint32_t)__cvta_generic_to_shared(&tile[0][0][0][0][0]);

        auto issue_pair = [&](int m) {
            const uint32_t pb = sbase + (uint32_t)(m % 3) * (TPAIRF * 4u);
            #pragma unroll
            for (int pl = 0; pl < 2; pl++) {
                const int zp   = zstart + 2 * m + pl;
                const bool zin = (unsigned)zp < (unsigned)D_;
                const int zoff = zin ? zp * HW_ : 0;
                const uint32_t tb = pb + (uint32_t)pl * (TPLANEF * 4u);
                #pragma unroll
                for (int sl = 0; sl < 4; sl++) {
                    if (umask & (1u << sl)) {
                        unsigned sz = (zin && (vmask & (1u << sl))) ? 8u : 0u;
                        cp_async8(tb + soffb[sl], gbase[sl] + zoff, sz);
                    }
                }
            }
            cp_commit();
        };

        // x-phase item covering BOTH planes of (row r, group g)
        auto xpair = [&](const float* pbuf, __half2* rsq, int item) {
            const int r = item >> 3;
            const int g = item & 7;
            const float* base0 = pbuf + r * 40 + 4 * g;
            __half2 keep[5][2];
            #pragma unroll
            for (int pl = 0; pl < 2; pl++) {
                const float* rowS = base0 + pl * TPLANEF;
                const float* rowT = rowS + TROWF;
                float4 a0 = *(const float4*)(rowS);
                float4 a1 = *(const float4*)(rowS + 4);
                float4 b0 = *(const float4*)(rowT);
                float4 b1 = *(const float4*)(rowT + 4);
                float sc[8] = {a0.x,a0.y,a0.z,a0.w,a1.x,a1.y,a1.z,a1.w};
                float tc[8] = {b0.x,b0.y,b0.z,b0.w,b1.x,b1.y,b1.z,b1.w};

                float V[5][4];
                {
                    float S0=0.f, T0=0.f, SS0=0.f, TT0=0.f, ST0=0.f;
                    #pragma unroll
                    for (int j = 0; j < 5; j++) {
                        S0 += sc[j]; T0 += tc[j];
                        SS0 = fmaf(sc[j], sc[j], SS0);
                        TT0 = fmaf(tc[j], tc[j], TT0);
                        ST0 = fmaf(sc[j], tc[j], ST0);
                    }
                    V[0][0]=S0; V[1][0]=T0; V[2][0]=SS0; V[3][0]=TT0; V[4][0]=ST0;
                    #pragma unroll
                    for (int w = 1; w < 4; w++) {
                        V[0][w] = V[0][w-1] - sc[w-1] + sc[w+4];
                        V[1][w] = V[1][w-1] - tc[w-1] + tc[w+4];
                        V[2][w] = V[2][w-1] - sc[w-1]*sc[w-1] + sc[w+4]*sc[w+4];
                        V[3][w] = V[3][w-1] - tc[w-1]*tc[w-1] + tc[w+4]*tc[w+4];
                        V[4][w] = V[4][w-1] - sc[w-1]*tc[w-1] + sc[w+4]*tc[w+4];
                    }
                }
                if (pl == 0) {
                    #pragma unroll
                    for (int c = 0; c < 5; c++) {
                        keep[c][0] = __floats2half2_rn(V[c][0], V[c][1]);
                        keep[c][1] = __floats2half2_rn(V[c][2], V[c][3]);
                    }
                } else {
                    #pragma unroll
                    for (int c = 0; c < 5; c++) {
                        union { __half2 h[4]; uint4 u; } pk;
                        pk.h[0] = keep[c][0];
                        pk.h[1] = __floats2half2_rn(V[c][0], V[c][1]);
                        pk.h[2] = keep[c][1];
                        pk.h[3] = __floats2half2_rn(V[c][2], V[c][3]);
                        *reinterpret_cast<uint4*>(rsq + c * RSCH + r * RSROW + 4 * g)
                            = pk.u;
                    }
                }
            }
        };

        issue_pair(0);
        issue_pair(1);

        for (int k = 0; k < NPAIRS; k++) {
            const int q = k & 1;
            bar_sync_n(BAR_EMPTY0 + q, NTHREADS);
            issue_pair(k + 2);
            cp_wait2();
            bar_sync_n(BAR_PROD, NPROD);

            if (tid < 96)
                xpair(&tile[k % 3][0][0][0][0], &rs[q][0], tid);

            bar_arrive_n(BAR_FULL0 + q, NTHREADS);
        }
    } else {
        // ===================== CONSUMER (128), pipelined =====================
        const int ctid = tid - NPROD;
        const int ctx2 = ctid & 15;              // consume: x-pair
        const int cty  = ctid >> 4;              // consume: output row
        const int ych  = ctid >> 4;              // y-phase: channel (<80 only)
        const int yx2  = ctid & 15;              // y-phase: x2 column

        float2 ring[5][5];      // [slot][ch], x-pair packed (fp32 delay line)
        float2 run[5];
        #pragma unroll
        for (int s = 0; s < 5; s++)
            #pragma unroll
            for (int c = 0; c < 5; c++) ring[s][c] = make_float2(0.f, 0.f);
        #pragma unroll
        for (int c = 0; c < 5; c++) run[c] = make_float2(0.f, 0.f);

        bar_arrive_n(BAR_EMPTY0, NTHREADS);
        bar_arrive_n(BAR_EMPTY1, NTHREADS);

        auto epilogue = [&]() {
            const float inv = 1.f / 125.f;
            #pragma unroll
            for (int e = 0; e < 2; e++) {
                float rS  = e ? run[0].y : run[0].x;
                float rT  = e ? run[1].y : run[1].x;
                float rSS = e ? run[2].y : run[2].x;
                float rTT = e ? run[3].y : run[3].x;
                float rST = e ? run[4].y : run[4].x;
                float sm = rS * inv;
                float tm = rT * inv;
                float sv = fmaf(-sm, sm, rSS * inv);
                float tv = fmaf(-tm, tm, rTT * inv);
                float cr = fmaf(-sm, tm, rST * inv);
                float den = fmaf(sv, tv, 1e-5f);
                acc += __fdividef(cr * cr, den);
            }
        };

        // y-phase: one (ch, x2) column; rs[q] rows -> ys[q] 8 output rows
        auto yphase = [&](const __half2* rq, __half2* yo5) {
            const __half2* col = rq + ych * RSCH + yx2 * 2;
            __half2* yo = yo5 + ych * YSCH + yx2 * 2;
            __half2 h0[5], h1[5];
            #pragma unroll
            for (int i = 0; i < 5; i++)
                lds_h2x2(col + i * RSROW, h0[i], h1[i]);
            __half2 n0 = __hadd2(__hadd2(__hadd2(h0[0], h0[1]),
                                         __hadd2(h0[2], h0[3])), h0[4]);
            __half2 n1 = __hadd2(__hadd2(__hadd2(h1[0], h1[1]),
                                         __hadd2(h1[2], h1[3])), h1[4]);
            sts_h2x2(yo, n0, n1);
            #pragma unroll
            for (int i = 5; i < 12; i++) {
                __half2 t0, t1;
                lds_h2x2(col + i * RSROW, t0, t1);
                n0 = __hadd2(__hsub2(n0, h0[i % 5]), t0);
                n1 = __hadd2(__hsub2(n1, h1[i % 5]), t1);
                h0[i % 5] = t0;
                h1[i % 5] = t1;
                sts_h2x2(yo + (i - 4) * YSROW, n0, n1);
            }
        };

        // consume pair p from ys buffer; slots s0 (plane 2p), s1 (plane 2p+1)
        auto consume = [&](const __half2* ysrc, int s0, int s1, bool live) {
            __half2 v0[5], v1[5];
            #pragma unroll
            for (int c = 0; c < 5; c++)
                lds_h2x2(ysrc + c * YSCH + cty * YSROW + ctx2 * 2, v0[c], v1[c]);
            #pragma unroll
            for (int c = 0; c < 5; c++) {
                float2 f = __half22float2(v0[c]);
                float2 o = ring[s0][c];
                run[c].x += f.x - o.x;
                run[c].y += f.y - o.y;
                ring[s0][c] = f;
            }
            if (live) epilogue();            // plane 2p
            #pragma unroll
            for (int c = 0; c < 5; c++) {
                float2 f = __half22float2(v1[c]);
                float2 o = ring[s1][c];
                run[c].x += f.x - o.x;
                run[c].y += f.y - o.y;
                ring[s1][c] = f;
            }
            if (live) epilogue();            // plane 2p+1
        };

        // 43 iterations: y-phase pair k (k<42), consume pair k-1 (k>=1)
        for (int kb = 0; kb <= 40; kb += 5) {
            #pragma unroll
            for (int jj = 0; jj < 5; jj++) {
                const int k = kb + jj;
                if (k > NPAIRS) break;       // allow k == 42 (drain)
                const int q = k & 1;
                // consumed pair p = k-1; slots (2p)%5, (2p+1)%5 (kb%5==0)
                const int s0 = (2 * jj + 3) % 5;
                const int s1 = (2 * jj + 4) % 5;

                if (k < NPAIRS) {
                    bar_sync_n(BAR_FULL0 + q, NTHREADS);
                    if (ctid < 80)
                        yphase(&rs[q][0], &ys[q][0]);
                    bar_arrive_n(BAR_EMPTY0 + q, NTHREADS);  // rs[q] free
                }
                if (k >= 1)
                    consume(&ys[q ^ 1][0], s0, s1, k >= 3);
                if (k < NPAIRS)
                    bar_sync_n(BAR_CONS, 128);   // publish ys[q] for next iter
            }
        }
    }

    // ---- block reduction over all 256 threads (producers contribute 0) ----
    __syncthreads();
    #pragma unroll
    for (int o = 16; o > 0; o >>= 1)
        acc += __shfl_xor_sync(0xffffffffu, acc, o);
    if ((tid & 31) == 0) wsum[tid >> 5] = acc;
    __syncthreads();

    if (tid == 0) {
        float bsum = 0.f;
        #pragma unroll
        for (int i = 0; i < 8; i++) bsum += wsum[i];
        atomicAdd(&g_acc, (double)bsum);
        __threadfence();
        unsigned done = atomicAdd(&g_cnt, 1u);
        if (done == NBLOCKS - 1) {
            double total = atomicAdd(&g_acc, 0.0);  // fenced read
            const double n = 2.0 * 160.0 * 192.0 * 192.0;
            float loss = (float)(1.0 - total / n);
            if (isnan(loss) || isinf(loss)) loss = 1.0f;
            out[0] = loss;
            *((volatile double*)&g_acc)   = 0.0;
            *((volatile unsigned*)&g_cnt) = 0u;
        }
    }
}

extern "C" void kernel_launch(void* const* d_in, const int* in_sizes, int n_in,
                              void* d_out, int out_size)
{
    (void)in_sizes; (void)n_in; (void)out_size;
    const float* src = (const float*)d_in[0];
    const float* tgt = (const float*)d_in[1];

    lncc_k<<<dim3(6, 24, 4), NTHREADS>>>(src, tgt, (float*)d_out);
}